// round 1
// baseline (speedup 1.0000x reference)
#include <cuda_runtime.h>
#include <cuda_bf16.h>

#define NPTS   65536
#define CHN    256
#define BATCH  16
#define LOUT   8192      // output length per sample (power of 2)
#define LOG2L  13

__device__ int g_counts[BATCH];
__device__ int g_offsets[BATCH];

// ---------------------------------------------------------------- setup ----
__global__ void zero_counts_kernel() {
    if (threadIdx.x < BATCH) g_counts[threadIdx.x] = 0;
}

__global__ void count_kernel(const int* __restrict__ batch) {
    __shared__ int sc[BATCH];
    if (threadIdx.x < BATCH) sc[threadIdx.x] = 0;
    __syncthreads();
    for (int i = blockIdx.x * blockDim.x + threadIdx.x; i < NPTS;
         i += gridDim.x * blockDim.x) {
        atomicAdd(&sc[batch[i]], 1);
    }
    __syncthreads();
    if (threadIdx.x < BATCH) {
        int v = sc[threadIdx.x];
        if (v) atomicAdd(&g_counts[threadIdx.x], v);
    }
}

__global__ void offsets_kernel() {
    if (threadIdx.x == 0) {
        int acc = 0;
        for (int b = 0; b < BATCH; b++) {
            g_offsets[b] = acc;
            acc += g_counts[b];
        }
    }
}

// ------------------------------------------------------------- points ------
// out_point[b, d, j] = points_x[src(b,j)*3 + d]; total 16*3*8192 elements.
// Warp covers 32 consecutive j for a fixed (b,d): coalesced 128B writes.
// points_x is 768 KB -> fully L2 resident after first touch.
__global__ void points_kernel(const float* __restrict__ px,
                              float* __restrict__ out) {
    int idx = blockIdx.x * blockDim.x + threadIdx.x;
    if (idx >= BATCH * 3 * LOUT) return;
    int j = idx & (LOUT - 1);
    int d = (idx >> LOG2L) % 3;
    int b = idx / (3 * LOUT);
    int cnt = g_counts[b];
    int off = g_offsets[b];
    int src = off + (int)(((unsigned)j * (unsigned)cnt) >> LOG2L);
    out[idx] = px[src * 3 + d];
}

// ------------------------------------------------------------ features -----
// out_feature[b, c, j] = feat[src(b,j), c]  -- gather + transpose.
// 32x32 smem tile: load = 128B coalesced row reads, store = 128B coalesced
// column writes along j. +1 pad kills bank conflicts on the transposed read.
#define TJ 32
#define TC 32

__global__ __launch_bounds__(256)
void feat_kernel(const float* __restrict__ feat, float* __restrict__ out) {
    __shared__ float tile[TJ][TC + 1];
    __shared__ int   s_src[TJ];

    int b  = blockIdx.z;
    int c0 = blockIdx.y * TC;
    int j0 = blockIdx.x * TJ;
    int tx = threadIdx.x;        // 0..31
    int ty = threadIdx.y;        // 0..7

    if (ty == 0) {
        int cnt = g_counts[b];
        int off = g_offsets[b];
        int j = j0 + tx;
        s_src[tx] = off + (int)(((unsigned)j * (unsigned)cnt) >> LOG2L);
    }
    __syncthreads();

    // Load: each warp reads one feature row segment (32 floats, 128B).
    #pragma unroll
    for (int jj = 0; jj < TJ; jj += 8) {
        int jl = jj + ty;
        tile[jl][tx] = feat[(size_t)s_src[jl] * CHN + c0 + tx];
    }
    __syncthreads();

    // Store: warp writes 32 consecutive j for one channel (128B coalesced).
    #pragma unroll
    for (int cc = 0; cc < TC; cc += 8) {
        int cl = cc + ty;
        out[(size_t)(b * CHN + c0 + cl) * LOUT + j0 + tx] = tile[tx][cl];
    }
}

// ------------------------------------------------------------- launch ------
extern "C" void kernel_launch(void* const* d_in, const int* in_sizes, int n_in,
                              void* d_out, int out_size) {
    const float* points_x = (const float*)d_in[0];   // [N,3]
    const float* feat     = (const float*)d_in[1];   // [N,C]
    const int*   batch    = (const int*)d_in[2];     // [N]

    float* out_point = (float*)d_out;                          // [B,3,L]
    float* out_feat  = (float*)d_out + (size_t)BATCH * 3 * LOUT; // [B,C,L]

    zero_counts_kernel<<<1, 32>>>();
    count_kernel<<<64, 256>>>(batch);
    offsets_kernel<<<1, 32>>>();

    int npt = BATCH * 3 * LOUT;
    points_kernel<<<(npt + 255) / 256, 256>>>(points_x, out_point);

    dim3 grid(LOUT / TJ, CHN / TC, BATCH);   // (256, 8, 16)
    dim3 blk(32, 8);
    feat_kernel<<<grid, blk>>>(feat, out_feat);
}

// round 2
// speedup vs baseline: 1.8656x; 1.8656x over previous
#include <cuda_runtime.h>
#include <cuda_bf16.h>

#define NPTS   65536
#define CHN    256
#define BATCH  16
#define LOUT   8192
#define LOG2L  13

// g_off[b] = first global index with batch id >= b; g_off[BATCH] = NPTS.
__device__ int g_off[BATCH + 1];

// ------------------------------------------------------- boundary detect ---
// batch is sorted; detect run boundaries, no atomics, fully parallel.
__global__ void boundary_kernel(const int* __restrict__ batch) {
    int t = blockIdx.x * blockDim.x + threadIdx.x;   // 0 .. NPTS/4-1
    if (t >= NPTS / 4) return;
    int4 v = ((const int4*)batch)[t];
    int prev = (t == 0) ? -1 : __ldg(&batch[4 * t - 1]);
    int a0 = prev, a1 = v.x, a2 = v.y, a3 = v.z, a4 = v.w;
    for (int bb = a0 + 1; bb <= a1; bb++) g_off[bb] = 4 * t + 0;
    for (int bb = a1 + 1; bb <= a2; bb++) g_off[bb] = 4 * t + 1;
    for (int bb = a2 + 1; bb <= a3; bb++) g_off[bb] = 4 * t + 2;
    for (int bb = a3 + 1; bb <= a4; bb++) g_off[bb] = 4 * t + 3;
    if (t == NPTS / 4 - 1) {
        for (int bb = a4 + 1; bb <= BATCH; bb++) g_off[bb] = NPTS;
    }
}

// ------------------------------------------------------------- points ------
// Each thread handles 4 consecutive j for one b: float4 coalesced stores to
// the three output planes; px reads have ~2x j->src locality (L1/L2 friendly).
__global__ void points_kernel(const float* __restrict__ px,
                              float* __restrict__ out) {
    int idx = blockIdx.x * blockDim.x + threadIdx.x;  // 0 .. B*L/4-1
    if (idx >= BATCH * LOUT / 4) return;
    int j = (idx & (LOUT / 4 - 1)) * 4;
    int b = idx >> (LOG2L - 2);
    int off = g_off[b];
    int cnt = g_off[b + 1] - off;
    float4 ox, oy, oz;
    #pragma unroll
    for (int t = 0; t < 4; t++) {
        int src = off + (int)(((unsigned)((j + t) * cnt)) >> LOG2L);
        const float* p = px + 3 * src;
        ((float*)&ox)[t] = p[0];
        ((float*)&oy)[t] = p[1];
        ((float*)&oz)[t] = p[2];
    }
    size_t base = (size_t)b * 3 * LOUT + j;
    *(float4*)(out + base)            = ox;
    *(float4*)(out + base + LOUT)     = oy;
    *(float4*)(out + base + 2 * LOUT) = oz;
}

// ------------------------------------------------------------ features -----
// 128(j) x 32(c) tile, 256 threads.
// Load:  4x LDG.128 per thread; each 8-lane group reads 128B of one row.
// STS:   banks {r + 4*c4 + i} cover all 32 -> conflict-free.
// Store: warp owns 4 channels; LDS stride 33 (odd) -> conflict-free;
//        STG.32 with lane-consecutive j -> 128B coalesced.
#define TJ 128
#define TC 32

__global__ __launch_bounds__(256)
void feat_kernel(const float4* __restrict__ feat4, float* __restrict__ out) {
    __shared__ float tile[TJ][TC + 1];
    __shared__ int   s_src[TJ];

    int b  = blockIdx.z;
    int c0 = blockIdx.y * TC;
    int j0 = blockIdx.x * TJ;
    int tid = threadIdx.x;

    if (tid < TJ) {
        int off = g_off[b];
        int cnt = g_off[b + 1] - off;
        int j = j0 + tid;
        s_src[tid] = off + (int)(((unsigned)(j * cnt)) >> LOG2L);
    }
    __syncthreads();

    int c4base = c0 >> 2;   // float4 column base within a feature row (64 f4/row)
    #pragma unroll
    for (int k = 0; k < 4; k++) {
        int idx = tid + k * 256;
        int row = idx >> 3;          // 0..127
        int c4  = idx & 7;           // 0..7
        float4 v = feat4[(size_t)s_src[row] * (CHN / 4) + c4base + c4];
        tile[row][c4 * 4 + 0] = v.x;
        tile[row][c4 * 4 + 1] = v.y;
        tile[row][c4 * 4 + 2] = v.z;
        tile[row][c4 * 4 + 3] = v.w;
    }
    __syncthreads();

    int lane = tid & 31;
    int w    = tid >> 5;             // 0..7
    #pragma unroll
    for (int k = 0; k < 4; k++) {
        int c = w * 4 + k;           // 0..31
        float* orow = out + (size_t)(b * CHN + c0 + c) * LOUT + j0;
        #pragma unroll
        for (int i = 0; i < 4; i++) {
            int j = lane + 32 * i;
            orow[j] = tile[j][c];
        }
    }
}

// ------------------------------------------------------------- launch ------
extern "C" void kernel_launch(void* const* d_in, const int* in_sizes, int n_in,
                              void* d_out, int out_size) {
    const float* points_x = (const float*)d_in[0];   // [N,3]
    const float* feat     = (const float*)d_in[1];   // [N,C]
    const int*   batch    = (const int*)d_in[2];     // [N]

    float* out_point = (float*)d_out;                              // [B,3,L]
    float* out_feat  = (float*)d_out + (size_t)BATCH * 3 * LOUT;   // [B,C,L]

    boundary_kernel<<<(NPTS / 4 + 255) / 256, 256>>>(batch);

    int npt = BATCH * LOUT / 4;
    points_kernel<<<(npt + 255) / 256, 256>>>(points_x, out_point);

    dim3 grid(LOUT / TJ, CHN / TC, BATCH);   // (64, 8, 16)
    feat_kernel<<<grid, 256>>>((const float4*)feat, out_feat);
}